// round 4
// baseline (speedup 1.0000x reference)
#include <cuda_runtime.h>
#include <cstdint>

#define NN 40000
#define EE 640000
#define DIM 128
#define NB 157   // ceil(40000/256)

// Scratch (static device globals — no allocation)
__device__ float g_hs[NN * DIM];   // h @ W (scaled by dinv[row] for layers 1,2)
__device__ float g_h[NN * DIM];    // layer output
__device__ float g_dinv[NN];
__device__ int   g_cnt[NN];
__device__ int   g_off[NN];
__device__ int   g_pos[NN];
__device__ int   g_ssrc[EE];       // edge srcs sorted by dst (CSR)
__device__ int   g_bsum[NB];
__device__ int   g_bbase[NB];

// ---------------- degree / CSR build ----------------

__global__ void zero_k() {
    int i = blockIdx.x * blockDim.x + threadIdx.x;
    if (i < NN) g_cnt[i] = 0;
}

__global__ void count_k(const int* __restrict__ dst) {
    int e = blockIdx.x * blockDim.x + threadIdx.x;
    if (e < EE) atomicAdd(&g_cnt[dst[e]], 1);
}

// block sums for scan + dinv fused
__global__ void scan1_k() {
    __shared__ int s[256];
    int i = blockIdx.x * 256 + threadIdx.x;
    int c = (i < NN) ? g_cnt[i] : 0;
    if (i < NN) g_dinv[i] = rsqrtf(1.0f + (float)c);
    s[threadIdx.x] = c;
    __syncthreads();
    for (int o = 128; o > 0; o >>= 1) {
        if (threadIdx.x < o) s[threadIdx.x] += s[threadIdx.x + o];
        __syncthreads();
    }
    if (threadIdx.x == 0) g_bsum[blockIdx.x] = s[0];
}

__global__ void scan2_k() {
    __shared__ int s[256];
    int t = threadIdx.x;
    int v = (t < NB) ? g_bsum[t] : 0;
    s[t] = v;
    __syncthreads();
    for (int o = 1; o < 256; o <<= 1) {
        int add = (t >= o) ? s[t - o] : 0;
        __syncthreads();
        s[t] += add;
        __syncthreads();
    }
    if (t < NB) g_bbase[t] = s[t] - v;   // exclusive base per chunk
}

__global__ void scan3_k() {
    __shared__ int s[256];
    int t = threadIdx.x;
    int i = blockIdx.x * 256 + t;
    int v = (i < NN) ? g_cnt[i] : 0;
    s[t] = v;
    __syncthreads();
    for (int o = 1; o < 256; o <<= 1) {
        int add = (t >= o) ? s[t - o] : 0;
        __syncthreads();
        s[t] += add;
        __syncthreads();
    }
    if (i < NN) {
        int off = g_bbase[blockIdx.x] + s[t] - v;  // exclusive prefix
        g_off[i] = off;
        g_pos[i] = off;
    }
}

__global__ void place_k(const int* __restrict__ src, const int* __restrict__ dst) {
    int e = blockIdx.x * blockDim.x + threadIdx.x;
    if (e < EE) {
        int d = dst[e];
        int p = atomicAdd(&g_pos[d], 1);
        g_ssrc[p] = src[e];
    }
}

// ---------------- tf32 tensor-core GEMM: g_hs = (A @ W) [* dinv[row] if SCALE] ----------------

__device__ __forceinline__ uint32_t f2tf32(float f) {
    uint32_t r;
    asm("cvt.rna.tf32.f32 %0, %1;" : "=r"(r) : "f"(f));
    return r;
}

#define SM_STRIDE 132
#define GEMM_SMEM (2 * 128 * SM_STRIDE * 4)

template <bool FROM_H, bool SCALE>
__global__ void gemm_tc(const float* __restrict__ Ax, const float* __restrict__ W) {
    const float* __restrict__ A = FROM_H ? (const float*)g_h : Ax;
    extern __shared__ uint32_t sm[];
    uint32_t* sA = sm;                    // [128][132]
    uint32_t* sW = sm + 128 * SM_STRIDE;  // [128][132]

    int tid = threadIdx.x;
    int r0 = blockIdx.x * 128;

    #pragma unroll
    for (int i = tid; i < 128 * 32; i += 256) {
        int k = i >> 5, c4 = (i & 31) << 2;
        float4 v = *(const float4*)&W[k * DIM + c4];
        uint32_t* p = &sW[k * SM_STRIDE + c4];
        p[0] = f2tf32(v.x); p[1] = f2tf32(v.y); p[2] = f2tf32(v.z); p[3] = f2tf32(v.w);
    }
    #pragma unroll
    for (int i = tid; i < 128 * 32; i += 256) {
        int r = i >> 5, c4 = (i & 31) << 2;
        int rr = min(r0 + r, NN - 1);
        float4 v = *(const float4*)&A[rr * DIM + c4];
        uint32_t* p = &sA[r * SM_STRIDE + c4];
        p[0] = f2tf32(v.x); p[1] = f2tf32(v.y); p[2] = f2tf32(v.z); p[3] = f2tf32(v.w);
    }
    __syncthreads();

    int warp = tid >> 5, lane = tid & 31;
    int g = lane >> 2, tg = lane & 3;
    int rbase = warp * 16;

    float c[16][4];
    #pragma unroll
    for (int nt = 0; nt < 16; nt++) {
        c[nt][0] = 0.f; c[nt][1] = 0.f; c[nt][2] = 0.f; c[nt][3] = 0.f;
    }

    #pragma unroll
    for (int kt = 0; kt < 16; kt++) {
        int k0 = kt * 8;
        uint32_t a0 = sA[(rbase + g) * SM_STRIDE + k0 + tg];
        uint32_t a1 = sA[(rbase + g + 8) * SM_STRIDE + k0 + tg];
        uint32_t a2 = sA[(rbase + g) * SM_STRIDE + k0 + tg + 4];
        uint32_t a3 = sA[(rbase + g + 8) * SM_STRIDE + k0 + tg + 4];
        #pragma unroll
        for (int nt = 0; nt < 16; nt++) {
            uint32_t b0 = sW[(k0 + tg) * SM_STRIDE + nt * 8 + g];
            uint32_t b1 = sW[(k0 + tg + 4) * SM_STRIDE + nt * 8 + g];
            asm volatile(
                "mma.sync.aligned.m16n8k8.row.col.f32.tf32.tf32.f32 "
                "{%0,%1,%2,%3}, {%4,%5,%6,%7}, {%8,%9}, {%0,%1,%2,%3};\n"
                : "+f"(c[nt][0]), "+f"(c[nt][1]), "+f"(c[nt][2]), "+f"(c[nt][3])
                : "r"(a0), "r"(a1), "r"(a2), "r"(a3), "r"(b0), "r"(b1));
        }
    }

    int row0 = r0 + rbase + g;
    int row1 = row0 + 8;
    float d0 = 1.f, d1 = 1.f;
    if (SCALE) {   // layer 0 must NOT touch g_dinv (CSR chain runs concurrently)
        d0 = (row0 < NN) ? g_dinv[row0] : 0.f;
        d1 = (row1 < NN) ? g_dinv[row1] : 0.f;
    }
    #pragma unroll
    for (int nt = 0; nt < 16; nt++) {
        int col = nt * 8 + 2 * tg;
        if (row0 < NN) {
            float2 o; o.x = c[nt][0] * d0; o.y = c[nt][1] * d0;
            *(float2*)&g_hs[row0 * DIM + col] = o;
        }
        if (row1 < NN) {
            float2 o; o.x = c[nt][2] * d1; o.y = c[nt][3] * d1;
            *(float2*)&g_hs[row1 * DIM + col] = o;
        }
    }
}

// ---------------- Aggregation: 4 warps per node (32-col chunks) ----------------
// SCALE_SRC (layer 0): hs is unscaled -> multiply gathered rows by dinv[s], self by dinv[w].
// h_out = relu(dinv[w]*(sum + self) + b); FINAL also projects to scalar.

template <bool SCALE_SRC, bool FINAL>
__global__ void agg_c(const float* __restrict__ bias,
                      const float* __restrict__ lw,
                      const float* __restrict__ lb,
                      float* __restrict__ out) {
    __shared__ float sred[8];
    int gw = (blockIdx.x * blockDim.x + threadIdx.x) >> 5;
    int node = gw >> 2;
    int lane = threadIdx.x & 31;
    int col = ((gw & 3) << 5) + lane;

    float acc = 0.f;
    int beg = g_off[node];
    int n = g_cnt[node];
    #pragma unroll 4
    for (int e = beg; e < beg + n; e++) {
        int s = g_ssrc[e];
        float v = g_hs[s * DIM + col];
        if (SCALE_SRC) v *= g_dinv[s];
        acc += v;
    }
    float di = g_dinv[node];
    float self = g_hs[node * DIM + col];
    if (SCALE_SRC) self *= di;
    float r = fmaxf(di * (acc + self) + bias[col], 0.f);

    if (FINAL) {
        float p = r * lw[col];
        #pragma unroll
        for (int o = 16; o > 0; o >>= 1) p += __shfl_xor_sync(0xffffffffu, p, o);
        int wl = threadIdx.x >> 5;
        if (lane == 0) sred[wl] = p;
        __syncthreads();
        if ((threadIdx.x & 127) == 0) {
            float t = sred[wl] + sred[wl + 1] + sred[wl + 2] + sred[wl + 3];
            out[node] = t + lb[0];
        }
    } else {
        g_h[node * DIM + col] = r;
    }
}

// ---------------- launch ----------------

extern "C" void kernel_launch(void* const* d_in, const int* in_sizes, int n_in,
                              void* d_out, int out_size) {
    const float* x  = (const float*)d_in[0];
    const int*   ei = (const int*)d_in[1];
    const int*   src = ei;
    const int*   dst = ei + EE;
    const float* W0 = (const float*)d_in[2];
    const float* b0 = (const float*)d_in[3];
    const float* W1 = (const float*)d_in[4];
    const float* b1 = (const float*)d_in[5];
    const float* W2 = (const float*)d_in[6];
    const float* b2 = (const float*)d_in[7];
    const float* lw = (const float*)d_in[8];
    const float* lb = (const float*)d_in[9];
    float* out = (float*)d_out;

    static cudaStream_t s2 = nullptr;
    static cudaEvent_t evFork = nullptr, evJoin = nullptr;
    if (s2 == nullptr) {
        cudaStreamCreateWithFlags(&s2, cudaStreamNonBlocking);
        cudaEventCreateWithFlags(&evFork, cudaEventDisableTiming);
        cudaEventCreateWithFlags(&evJoin, cudaEventDisableTiming);
        cudaFuncSetAttribute(gemm_tc<false, false>, cudaFuncAttributeMaxDynamicSharedMemorySize, GEMM_SMEM);
        cudaFuncSetAttribute(gemm_tc<true, true>,   cudaFuncAttributeMaxDynamicSharedMemorySize, GEMM_SMEM);
    }

    const int GEMM_BLOCKS = (NN + 127) / 128;       // 313
    const int AGG_BLOCKS = (NN * 4 * 32) / 256;     // 4 warps per node, 256-thread blocks

    // Fork: CSR build on s2, concurrent with layer-0 GEMM (which needs no dinv).
    cudaEventRecord(evFork, 0);
    cudaStreamWaitEvent(s2, evFork, 0);
    zero_k<<<NB, 256, 0, s2>>>();
    count_k<<<EE / 256, 256, 0, s2>>>(dst);
    scan1_k<<<NB, 256, 0, s2>>>();
    scan2_k<<<1, 256, 0, s2>>>();
    scan3_k<<<NB, 256, 0, s2>>>();
    place_k<<<EE / 256, 256, 0, s2>>>(src, dst);
    cudaEventRecord(evJoin, s2);

    gemm_tc<false, false><<<GEMM_BLOCKS, 256, GEMM_SMEM>>>(x, W0);   // hs0 = x @ W0 (unscaled)
    cudaStreamWaitEvent(0, evJoin, 0);                               // join before agg0

    // layer 0 (src-side dinv applied in agg)
    agg_c<true, false><<<AGG_BLOCKS, 256>>>(b0, nullptr, nullptr, nullptr);
    // layer 1
    gemm_tc<true, true><<<GEMM_BLOCKS, 256, GEMM_SMEM>>>(nullptr, W1);
    agg_c<false, false><<<AGG_BLOCKS, 256>>>(b1, nullptr, nullptr, nullptr);
    // layer 2 + final linear fused
    gemm_tc<true, true><<<GEMM_BLOCKS, 256, GEMM_SMEM>>>(nullptr, W2);
    agg_c<false, true><<<AGG_BLOCKS, 256>>>(b2, lw, lb, out);
}

// round 5
// speedup vs baseline: 1.4338x; 1.4338x over previous
#include <cuda_runtime.h>
#include <cstdint>

#define NN 40000
#define EE 640000
#define DIM 128
#define NB 157   // ceil(40000/256)

// Scratch (static device globals — no allocation)
__device__ float g_hs[NN * DIM];   // h @ W (pre-scaled by dinv[row] on layers 1,2)
__device__ float g_h[NN * DIM];    // layer output
__device__ float g_dinv[NN];
__device__ int   g_cnt[NN];
__device__ int   g_off[NN];
__device__ int   g_pos[NN];
__device__ int   g_ssrc[EE];       // edge srcs sorted by dst (CSR)
__device__ int   g_bsum[NB];

// ---------------- degree / CSR build (5 launches) ----------------

__global__ void zero_k() {
    int i = blockIdx.x * blockDim.x + threadIdx.x;
    if (i < NN) g_cnt[i] = 0;
}

__global__ void count_k(const int* __restrict__ dst) {
    int e = blockIdx.x * blockDim.x + threadIdx.x;
    if (e < EE) atomicAdd(&g_cnt[dst[e]], 1);
}

// block sums + dinv fused
__global__ void scan1_k() {
    __shared__ int s[256];
    int i = blockIdx.x * 256 + threadIdx.x;
    int c = (i < NN) ? g_cnt[i] : 0;
    if (i < NN) g_dinv[i] = rsqrtf(1.0f + (float)c);
    s[threadIdx.x] = c;
    __syncthreads();
    for (int o = 128; o > 0; o >>= 1) {
        if (threadIdx.x < o) s[threadIdx.x] += s[threadIdx.x + o];
        __syncthreads();
    }
    if (threadIdx.x == 0) g_bsum[blockIdx.x] = s[0];
}

// per-block base reduced inline (replaces old scan2) + intra-block scan
__global__ void scan3_k() {
    __shared__ int s[256];
    __shared__ int bb[256];
    int t = threadIdx.x;
    int i = blockIdx.x * 256 + t;

    int b = (t < blockIdx.x) ? g_bsum[t] : 0;   // blockIdx.x < 256 always
    bb[t] = b;
    int v = (i < NN) ? g_cnt[i] : 0;
    s[t] = v;
    __syncthreads();
    for (int o = 128; o > 0; o >>= 1) {
        if (t < o) bb[t] += bb[t + o];
        __syncthreads();
    }
    for (int o = 1; o < 256; o <<= 1) {
        int add = (t >= o) ? s[t - o] : 0;
        __syncthreads();
        s[t] += add;
        __syncthreads();
    }
    if (i < NN) {
        int off = bb[0] + s[t] - v;   // exclusive prefix
        g_off[i] = off;
        g_pos[i] = off;
    }
}

__global__ void place_k(const int* __restrict__ src, const int* __restrict__ dst) {
    int e = blockIdx.x * blockDim.x + threadIdx.x;
    if (e < EE) {
        int d = dst[e];
        int p = atomicAdd(&g_pos[d], 1);
        g_ssrc[p] = src[e];
    }
}

// ---------------- tf32 tensor-core GEMM: g_hs = (A @ W) [* dinv[row] if SCALE] ----------------

__device__ __forceinline__ uint32_t f2tf32(float f) {
    uint32_t r;
    asm("cvt.rna.tf32.f32 %0, %1;" : "=r"(r) : "f"(f));
    return r;
}

#define SM_STRIDE 132
#define GEMM_SMEM (2 * 128 * SM_STRIDE * 4)

template <bool FROM_H, bool SCALE>
__global__ void gemm_tc(const float* __restrict__ Ax, const float* __restrict__ W) {
    const float* __restrict__ A = FROM_H ? (const float*)g_h : Ax;
    extern __shared__ uint32_t sm[];
    uint32_t* sA = sm;                    // [128][132]
    uint32_t* sW = sm + 128 * SM_STRIDE;  // [128][132]

    int tid = threadIdx.x;
    int r0 = blockIdx.x * 128;

    #pragma unroll
    for (int i = tid; i < 128 * 32; i += 256) {
        int k = i >> 5, c4 = (i & 31) << 2;
        float4 v = *(const float4*)&W[k * DIM + c4];
        uint32_t* p = &sW[k * SM_STRIDE + c4];
        p[0] = f2tf32(v.x); p[1] = f2tf32(v.y); p[2] = f2tf32(v.z); p[3] = f2tf32(v.w);
    }
    #pragma unroll
    for (int i = tid; i < 128 * 32; i += 256) {
        int r = i >> 5, c4 = (i & 31) << 2;
        int rr = min(r0 + r, NN - 1);
        float4 v = *(const float4*)&A[rr * DIM + c4];
        uint32_t* p = &sA[r * SM_STRIDE + c4];
        p[0] = f2tf32(v.x); p[1] = f2tf32(v.y); p[2] = f2tf32(v.z); p[3] = f2tf32(v.w);
    }
    __syncthreads();

    int warp = tid >> 5, lane = tid & 31;
    int g = lane >> 2, tg = lane & 3;
    int rbase = warp * 16;

    float c[16][4];
    #pragma unroll
    for (int nt = 0; nt < 16; nt++) {
        c[nt][0] = 0.f; c[nt][1] = 0.f; c[nt][2] = 0.f; c[nt][3] = 0.f;
    }

    #pragma unroll
    for (int kt = 0; kt < 16; kt++) {
        int k0 = kt * 8;
        uint32_t a0 = sA[(rbase + g) * SM_STRIDE + k0 + tg];
        uint32_t a1 = sA[(rbase + g + 8) * SM_STRIDE + k0 + tg];
        uint32_t a2 = sA[(rbase + g) * SM_STRIDE + k0 + tg + 4];
        uint32_t a3 = sA[(rbase + g + 8) * SM_STRIDE + k0 + tg + 4];
        #pragma unroll
        for (int nt = 0; nt < 16; nt++) {
            uint32_t b0 = sW[(k0 + tg) * SM_STRIDE + nt * 8 + g];
            uint32_t b1 = sW[(k0 + tg + 4) * SM_STRIDE + nt * 8 + g];
            asm volatile(
                "mma.sync.aligned.m16n8k8.row.col.f32.tf32.tf32.f32 "
                "{%0,%1,%2,%3}, {%4,%5,%6,%7}, {%8,%9}, {%0,%1,%2,%3};\n"
                : "+f"(c[nt][0]), "+f"(c[nt][1]), "+f"(c[nt][2]), "+f"(c[nt][3])
                : "r"(a0), "r"(a1), "r"(a2), "r"(a3), "r"(b0), "r"(b1));
        }
    }

    int row0 = r0 + rbase + g;
    int row1 = row0 + 8;
    float d0 = 1.f, d1 = 1.f;
    if (SCALE) {   // layer 0 must NOT touch g_dinv (CSR chain runs concurrently)
        d0 = (row0 < NN) ? g_dinv[row0] : 0.f;
        d1 = (row1 < NN) ? g_dinv[row1] : 0.f;
    }
    #pragma unroll
    for (int nt = 0; nt < 16; nt++) {
        int col = nt * 8 + 2 * tg;
        if (row0 < NN) {
            float2 o; o.x = c[nt][0] * d0; o.y = c[nt][1] * d0;
            *(float2*)&g_hs[row0 * DIM + col] = o;
        }
        if (row1 < NN) {
            float2 o; o.x = c[nt][2] * d1; o.y = c[nt][3] * d1;
            *(float2*)&g_hs[row1 * DIM + col] = o;
        }
    }
}

// ---------------- Aggregation: one warp per node, float4 lanes ----------------
// SCALE_SRC (layer 0): hs unscaled -> per-edge broadcast dinv[s] multiply.
// h_out = relu(dinv[w]*(sum + self) + b); FINAL also projects to scalar.

template <bool SCALE_SRC, bool FINAL>
__global__ void agg_k(const float* __restrict__ bias,
                      const float* __restrict__ lw,
                      const float* __restrict__ lb,
                      float* __restrict__ out) {
    int w = (blockIdx.x * blockDim.x + threadIdx.x) >> 5;
    int lane = threadIdx.x & 31;
    if (w >= NN) return;
    int l4 = lane * 4;

    float4 acc = make_float4(0.f, 0.f, 0.f, 0.f);
    int beg = g_off[w];
    int n = g_cnt[w];
    #pragma unroll 4
    for (int e = beg; e < beg + n; e++) {
        int s = g_ssrc[e];
        float4 v = *(const float4*)&g_hs[s * DIM + l4];
        float sc = SCALE_SRC ? g_dinv[s] : 1.f;
        acc.x = fmaf(v.x, sc, acc.x);
        acc.y = fmaf(v.y, sc, acc.y);
        acc.z = fmaf(v.z, sc, acc.z);
        acc.w = fmaf(v.w, sc, acc.w);
    }
    float di = g_dinv[w];
    float4 self = *(const float4*)&g_hs[w * DIM + l4];
    float selfsc = SCALE_SRC ? di : 1.f;
    float4 bb = *(const float4*)&bias[l4];

    float4 r;
    r.x = fmaxf(di * (acc.x + self.x * selfsc) + bb.x, 0.f);
    r.y = fmaxf(di * (acc.y + self.y * selfsc) + bb.y, 0.f);
    r.z = fmaxf(di * (acc.z + self.z * selfsc) + bb.z, 0.f);
    r.w = fmaxf(di * (acc.w + self.w * selfsc) + bb.w, 0.f);

    if (FINAL) {
        float4 lwv = *(const float4*)&lw[l4];
        float p = r.x * lwv.x + r.y * lwv.y + r.z * lwv.z + r.w * lwv.w;
        #pragma unroll
        for (int o = 16; o > 0; o >>= 1) p += __shfl_xor_sync(0xffffffffu, p, o);
        if (lane == 0) out[w] = p + lb[0];
    } else {
        *(float4*)&g_h[w * DIM + l4] = r;
    }
}

// ---------------- launch ----------------

extern "C" void kernel_launch(void* const* d_in, const int* in_sizes, int n_in,
                              void* d_out, int out_size) {
    const float* x  = (const float*)d_in[0];
    const int*   ei = (const int*)d_in[1];
    const int*   src = ei;
    const int*   dst = ei + EE;
    const float* W0 = (const float*)d_in[2];
    const float* b0 = (const float*)d_in[3];
    const float* W1 = (const float*)d_in[4];
    const float* b1 = (const float*)d_in[5];
    const float* W2 = (const float*)d_in[6];
    const float* b2 = (const float*)d_in[7];
    const float* lw = (const float*)d_in[8];
    const float* lb = (const float*)d_in[9];
    float* out = (float*)d_out;

    static cudaStream_t s2 = nullptr;
    static cudaEvent_t evFork = nullptr, evJoin = nullptr;
    if (s2 == nullptr) {
        cudaStreamCreateWithFlags(&s2, cudaStreamNonBlocking);
        cudaEventCreateWithFlags(&evFork, cudaEventDisableTiming);
        cudaEventCreateWithFlags(&evJoin, cudaEventDisableTiming);
        cudaFuncSetAttribute(gemm_tc<false, false>, cudaFuncAttributeMaxDynamicSharedMemorySize, GEMM_SMEM);
        cudaFuncSetAttribute(gemm_tc<true, true>,   cudaFuncAttributeMaxDynamicSharedMemorySize, GEMM_SMEM);
    }

    const int GEMM_BLOCKS = (NN + 127) / 128;   // 313
    const int AGG_BLOCKS = (NN * 32) / 256;     // one warp per node

    // Fork: CSR build on s2, concurrent with layer-0 GEMM (which needs no dinv).
    cudaEventRecord(evFork, 0);
    cudaStreamWaitEvent(s2, evFork, 0);
    zero_k<<<NB, 256, 0, s2>>>();
    count_k<<<EE / 256, 256, 0, s2>>>(dst);
    scan1_k<<<NB, 256, 0, s2>>>();
    scan3_k<<<NB, 256, 0, s2>>>();
    place_k<<<EE / 256, 256, 0, s2>>>(src, dst);
    cudaEventRecord(evJoin, s2);

    gemm_tc<false, false><<<GEMM_BLOCKS, 256, GEMM_SMEM>>>(x, W0);   // hs0 = x @ W0 (unscaled)
    cudaStreamWaitEvent(0, evJoin, 0);                               // join before agg0

    // layer 0 (src-side dinv applied per edge, broadcast load)
    agg_k<true, false><<<AGG_BLOCKS, 256>>>(b0, nullptr, nullptr, nullptr);
    // layer 1
    gemm_tc<true, true><<<GEMM_BLOCKS, 256, GEMM_SMEM>>>(nullptr, W1);
    agg_k<false, false><<<AGG_BLOCKS, 256>>>(b1, nullptr, nullptr, nullptr);
    // layer 2 + final linear fused
    gemm_tc<true, true><<<GEMM_BLOCKS, 256, GEMM_SMEM>>>(nullptr, W2);
    agg_k<false, true><<<AGG_BLOCKS, 256>>>(b2, lw, lb, out);
}